// round 16
// baseline (speedup 1.0000x reference)
#include <cuda_runtime.h>
#include <cuda_fp16.h>
#include <cstdint>

// ---------------------------------------------------------------------------
// Problem constants
// ---------------------------------------------------------------------------
#define M_TOTAL 8192   // 4 * 2048
#define N_TOTAL 4096   // OUT_FEATURES
#define K_TOTAL 4096   // IN_FEATURES

#define M_BLKS (M_TOTAL / 128)     // 64
#define N_BLKS (N_TOTAL / 128)     // 32

// GEMM tiling
#define BM 256
#define BN 128
#define BK 64
#define STAGES 4
#define NKT (K_TOTAL / BK)         // 64

// Fragment-packed fp16 scratch.
// g_X4: [k16][m_blk128][mtile(8)][lane(32)] -> uint4 = A frag {a0,a1,a2,a3}
// g_W4: [k16][n_blk128][npair(8)][lane(32)] -> uint4 = {b0,b1 | n8=2p ; b0,b1 | n8=2p+1}
__device__ __align__(1024) uint4 g_X4[(size_t)M_TOTAL * K_TOTAL / 8];  // 64 MB
__device__ __align__(1024) uint4 g_W4[(size_t)N_TOTAL * K_TOTAL / 8];  // 32 MB

__constant__ float c_codebook[16] = {
    0.0f, 0.0052f, 0.6667f, 1.0f, 0.3333f, 0.5f, 0.1667f, 0.25f,
    0.0f, -0.0052f, -0.6667f, -1.0f, -0.3333f, -0.5f, -0.1667f, -0.25f};

__device__ __forceinline__ uint32_t pack_h2(float a, float b) {
    __half2 h = __floats2half2_rn(a, b);
    return *reinterpret_cast<uint32_t*>(&h);
}

__device__ __forceinline__ void cp_async16(void* smem_dst, const void* gsrc) {
    uint32_t d = (uint32_t)__cvta_generic_to_shared(smem_dst);
    asm volatile("cp.async.cg.shared.global [%0], [%1], 16;\n" ::"r"(d), "l"(gsrc));
}
__device__ __forceinline__ void cp_commit() {
    asm volatile("cp.async.commit_group;\n" ::: "memory");
}
template <int N>
__device__ __forceinline__ void cp_wait() {
    asm volatile("cp.async.wait_group %0;\n" ::"n"(N) : "memory");
}

// ---------------------------------------------------------------------------
// Kernel 1 (merged): pack X and dequant+pack W, overlapped in one launch.
// Grid (K_TOTAL/64 = 64, M_BLKS + N_BLKS = 96), 256 threads.
// Each CTA covers 128 rows x 64 k (4 k16 steps).
//   blockIdx.y <  64 : xpack  (mb = y)
//   blockIdx.y >= 64 : dequant (nb = y - 64)
// SMEM staging: __half s[128][72] (stride 72 halves = 36 banks -> the
// fragment-gather reads hit 32 distinct banks; verified (4*gr+gc+8*k16l)%32).
// ---------------------------------------------------------------------------
__global__ __launch_bounds__(256) void pack_all(const int4* __restrict__ wp4,
                                                const float* __restrict__ scale,
                                                const float4* __restrict__ x4) {
    __shared__ __align__(16) __half s[128][72];
    const int kb = blockIdx.x;          // 64-wide k chunk, 0..63
    const int yb = blockIdx.y;
    const int tid = threadIdx.x;

    if (yb < M_BLKS) {
        // ---------------- xpack: x -> fp16 A-fragment-major ----------------
        const int mb = yb;
        // Phase 1: coalesced read + convert. 2048 float4 per CTA, 8/thread.
#pragma unroll
        for (int j = 0; j < 8; j++) {
            const int idx = tid + j * 256;
            const int row = idx >> 4;
            const int c4 = idx & 15;
            float4 v = x4[(size_t)(mb * 128 + row) * (K_TOTAL / 4) + kb * 16 + c4];
            uint2 h;
            h.x = pack_h2(v.x, v.y);
            h.y = pack_h2(v.z, v.w);
            *reinterpret_cast<uint2*>(&s[row][c4 * 4]) = h;
        }
        __syncthreads();
        // Phase 2: emit A fragments. 4 k16 x 8 mtile x 32 lanes = 1024 uint4.
#pragma unroll
        for (int j = 0; j < 4; j++) {
            const int idx = tid + j * 256;
            const int k16l = idx >> 8;              // 0..3
            const int mt = (idx >> 5) & 7;
            const int lane = idx & 31;
            const int gr = lane >> 2, gc = lane & 3;
            const int c0 = k16l * 16 + 2 * gc;
            const int r0 = mt * 16 + gr;
            uint4 v;
            v.x = *reinterpret_cast<const uint32_t*>(&s[r0][c0]);         // a0
            v.y = *reinterpret_cast<const uint32_t*>(&s[r0 + 8][c0]);     // a1
            v.z = *reinterpret_cast<const uint32_t*>(&s[r0][c0 + 8]);     // a2
            v.w = *reinterpret_cast<const uint32_t*>(&s[r0 + 8][c0 + 8]); // a3
            g_X4[((size_t)(kb * 4 + k16l) * M_BLKS + mb) * 256 + mt * 32 + lane] = v;
        }
    } else {
        // ------------- dequant: packed FP4 -> fp16 B-fragment-major -------------
        const int nb = yb - M_BLKS;
        // Phase 1: 2 threads/row, 4 consecutive int4 each (MLP=4).
        // 64 k of a row lie inside one 64-wide scale block => one scale per row.
        {
            const int row = tid >> 1;
            const int half = tid & 1;
            const int ibase = (nb * 128 + row) * 2048 + kb * 32 + half * 16;  // int idx
            const float sc = scale[(nb * 128 + row) * 64 + kb];
            const int4* src = &wp4[ibase >> 2];
            int4 p[4];
#pragma unroll
            for (int q = 0; q < 4; q++) p[q] = src[q];   // batched: 4 loads in flight
#pragma unroll
            for (int q = 0; q < 4; q++) {
                uint4 h;
                h.x = pack_h2(c_codebook[(p[q].x >> 4) & 15] * sc,
                              c_codebook[p[q].x & 15] * sc);
                h.y = pack_h2(c_codebook[(p[q].y >> 4) & 15] * sc,
                              c_codebook[p[q].y & 15] * sc);
                h.z = pack_h2(c_codebook[(p[q].z >> 4) & 15] * sc,
                              c_codebook[p[q].z & 15] * sc);
                h.w = pack_h2(c_codebook[(p[q].w >> 4) & 15] * sc,
                              c_codebook[p[q].w & 15] * sc);
                *reinterpret_cast<uint4*>(&s[row][half * 32 + q * 8]) = h;
            }
        }
        __syncthreads();
        // Phase 2: emit B fragments. 4 k16 x 8 npair x 32 lanes = 1024 uint4.
#pragma unroll
        for (int j = 0; j < 4; j++) {
            const int idx = tid + j * 256;
            const int k16l = idx >> 8;
            const int np = (idx >> 5) & 7;
            const int lane = idx & 31;
            const int gr = lane >> 2, gc = lane & 3;
            const int c0 = k16l * 16 + 2 * gc;
            const int ra = np * 16 + gr;        // n8 = 2*np
            const int rb = np * 16 + 8 + gr;    // n8 = 2*np+1
            uint4 v;
            v.x = *reinterpret_cast<const uint32_t*>(&s[ra][c0]);
            v.y = *reinterpret_cast<const uint32_t*>(&s[ra][c0 + 8]);
            v.z = *reinterpret_cast<const uint32_t*>(&s[rb][c0]);
            v.w = *reinterpret_cast<const uint32_t*>(&s[rb][c0 + 8]);
            g_W4[((size_t)(kb * 4 + k16l) * N_BLKS + nb) * 256 + np * 32 + lane] = v;
        }
    }
}

// ---------------------------------------------------------------------------
// Kernel 2: GEMM  out = X @ W^T + bias   (fp16 inputs, fp32 accumulate)
// CTA 256x128, 512 threads (16 warps: 4m x 4n), warp tile 64x32.
// 4-stage cp.async ring (48 KB/stage, 192 KB), prefetch depth 3, wait<2>:
// two full stages of slack to absorb L2-latency jitter at wave fronts.
// ---------------------------------------------------------------------------
__global__ __launch_bounds__(512, 1) void gemm_h(const float* __restrict__ bias,
                                                 float* __restrict__ out) {
    extern __shared__ __align__(16) uint4 smem4[];
    uint4* As = smem4;                   // STAGES * 2048 uint4
    uint4* Bs = smem4 + STAGES * 2048;   // STAGES * 1024 uint4

    const int tid = threadIdx.x;
    const int wid = tid >> 5;
    const int lane = tid & 31;
    const int gr = lane >> 2, gc = lane & 3;
    const int warp_mt0 = (wid & 3) * 4;  // mtile base (of 16 mtiles x 16 rows)
    const int warp_np = (wid >> 2) * 2;  // npair base (of 8 npairs x 16 cols)
    const int mb = blockIdx.y;           // 256-row tile
    const int nb = blockIdx.x;           // 128-col tile

    auto load_stage = [&](int st, int kt) {
        // A: 8 chunks of 256 uint4 -> (k16 local 0..3) x (mblk half 0..1)
#pragma unroll
        for (int j = 0; j < 4; j++) {
            const int idx = tid + j * 512;
            const int chunk = idx >> 8;
            const int within = idx & 255;
            const int k16 = kt * 4 + (chunk >> 1);
            const int mblk = mb * 2 + (chunk & 1);
            cp_async16(&As[st * 2048 + idx],
                       &g_X4[((size_t)k16 * M_BLKS + mblk) * 256 + within]);
        }
        // B: 4 chunks of 256 uint4 -> k16 local 0..3
#pragma unroll
        for (int j = 0; j < 2; j++) {
            const int idx = tid + j * 512;
            const int k16 = kt * 4 + (idx >> 8);
            cp_async16(&Bs[st * 1024 + idx],
                       &g_W4[((size_t)k16 * N_BLKS + nb) * 256 + (idx & 255)]);
        }
        cp_commit();
    };

    float acc[4][4][4];
#pragma unroll
    for (int i = 0; i < 4; i++)
#pragma unroll
        for (int j = 0; j < 4; j++)
#pragma unroll
            for (int r = 0; r < 4; r++) acc[i][j][r] = 0.0f;

    load_stage(0, 0);
    load_stage(1, 1);
    load_stage(2, 2);

    int cur = 0;
    for (int kt = 0; kt < NKT; kt++) {
        cp_wait<2>();
        __syncthreads();
        if (kt + 3 < NKT) {
            int nxt = cur + 3; if (nxt >= STAGES) nxt -= STAGES;
            load_stage(nxt, kt + 3);
        } else {
            cp_commit();  // keep group count consistent for cp_wait<2>
        }

        const uint4* a_s = &As[cur * 2048];
        const uint4* b_s = &Bs[cur * 1024];
#pragma unroll
        for (int ks = 0; ks < 4; ks++) {
            uint4 af[4], bf[2];
#pragma unroll
            for (int tm = 0; tm < 4; tm++) {
                const int mt = warp_mt0 + tm;
                af[tm] = a_s[(ks * 2 + (mt >> 3)) * 256 + (mt & 7) * 32 + lane];
            }
#pragma unroll
            for (int p = 0; p < 2; p++)
                bf[p] = b_s[ks * 256 + (warp_np + p) * 32 + lane];
#pragma unroll
            for (int tm = 0; tm < 4; tm++) {
#pragma unroll
                for (int tn = 0; tn < 4; tn++) {
                    const uint4& bv = bf[tn >> 1];
                    const uint32_t b0 = (tn & 1) ? bv.z : bv.x;
                    const uint32_t b1 = (tn & 1) ? bv.w : bv.y;
                    asm volatile(
                        "mma.sync.aligned.m16n8k16.row.col.f32.f16.f16.f32 "
                        "{%0,%1,%2,%3}, {%4,%5,%6,%7}, {%8,%9}, {%0,%1,%2,%3};"
                        : "+f"(acc[tm][tn][0]), "+f"(acc[tm][tn][1]),
                          "+f"(acc[tm][tn][2]), "+f"(acc[tm][tn][3])
                        : "r"(af[tm].x), "r"(af[tm].y), "r"(af[tm].z), "r"(af[tm].w),
                          "r"(b0), "r"(b1));
                }
            }
        }
        cur++; if (cur >= STAGES) cur -= STAGES;
    }

    // Epilogue: add bias, float2 stores.
#pragma unroll
    for (int tm = 0; tm < 4; tm++) {
        const int m = mb * BM + (warp_mt0 + tm) * 16 + gr;
#pragma unroll
        for (int tn = 0; tn < 4; tn++) {
            const int p = tn >> 1, q = tn & 1;
            const int n = nb * BN + (warp_np + p) * 16 + q * 8 + gc * 2;
            const float b0 = __ldg(&bias[n]);
            const float b1 = __ldg(&bias[n + 1]);
            float2 v0 = make_float2(acc[tm][tn][0] + b0, acc[tm][tn][1] + b1);
            float2 v1 = make_float2(acc[tm][tn][2] + b0, acc[tm][tn][3] + b1);
            *reinterpret_cast<float2*>(&out[(size_t)m * N_TOTAL + n]) = v0;
            *reinterpret_cast<float2*>(&out[(size_t)(m + 8) * N_TOTAL + n]) = v1;
        }
    }
}

// ---------------------------------------------------------------------------
extern "C" void kernel_launch(void* const* d_in, const int* in_sizes, int n_in,
                              void* d_out, int out_size) {
    const float* x = (const float*)d_in[0];       // [4,2048,4096] fp32
    const int* wp = (const int*)d_in[1];          // [8388608] int32 (one byte each)
    const float* scale = (const float*)d_in[2];   // [262144] fp32
    const float* bias = (const float*)d_in[3];    // [4096] fp32
    float* out = (float*)d_out;                   // [4,2048,4096] fp32

    pack_all<<<dim3(K_TOTAL / 64, M_BLKS + N_BLKS), 256>>>(
        (const int4*)wp, scale, (const float4*)x);

    const int smem_bytes = STAGES * (2048 + 1024) * sizeof(uint4);  // 196608
    static bool attr_set = false;
    if (!attr_set) {
        cudaFuncSetAttribute(gemm_h, cudaFuncAttributeMaxDynamicSharedMemorySize,
                             smem_bytes);
        attr_set = true;
    }
    dim3 grid(N_TOTAL / BN, M_TOTAL / BM);  // (32, 32)
    gemm_h<<<grid, 512, smem_bytes>>>(bias, out);
}